// round 16
// baseline (speedup 1.0000x reference)
#include <cuda_runtime.h>

// Problem constants (match reference)
#define Bb   2
#define NGT  64
#define Gp   6
#define G3   216            // Gp^3
#define Cc   64
#define DZ   10
#define DY   400
#define DX   352
#define NPTS (Bb*NGT*G3)    // 27648 grid points (per branch)
#define NMAP (Bb*DZ*DY*DX)  // 2,816,000 cells
#define RR   (Bb*NGT)       // 128 ROIs

// Scratch (static device globals — no allocation allowed)
__device__ int   g_v2p[2][NMAP];       // voxel->point index map, -1 = empty
__device__ float g_pooled[2][NPTS*Cc]; // per-grid-point pooled feature
__device__ float g_roi[RR];            // per-ROI |cosine|

// ---------------------------------------------------------------------------
// Scatter voxel index into dense map. atomicMax == last-write-wins for the
// ascending arange the reference scatters (matches XLA CPU scatter order).
// blockIdx.y selects branch (0=dir, 1=dsr).
// ---------------------------------------------------------------------------
__global__ void scatter_kernel(const int* __restrict__ c0,
                               const int* __restrict__ c1, int ntot) {
    int i = blockIdx.x * blockDim.x + threadIdx.x;
    if (i >= ntot) return;
    const int* c = (blockIdx.y ? c1 : c0) + (size_t)i * 4;
    int flat = ((c[0] * DZ + c[1]) * DY + c[2]) * DX + c[3];
    atomicMax(&g_v2p[blockIdx.y][flat], i);
}

// ---------------------------------------------------------------------------
// Pooling: one block per (grid point, branch). 64 threads = one per channel.
// Threads 0..26 resolve the 27 neighbor cells into shared, then every thread
// accumulates its channel over the valid neighbors.
// ---------------------------------------------------------------------------
__global__ __launch_bounds__(64)
void pool_kernel(const float* __restrict__ gt,
                 const float* __restrict__ f0,
                 const float* __restrict__ f1) {
    int m  = blockIdx.x;
    int br = blockIdx.y;
    const float* feats = br ? f1 : f0;

    int r = m / G3;
    int j = m - r * G3;
    int b = r / NGT;

    const float* roi = gt + (size_t)r * 8;
    float cx = roi[0], cy = roi[1], cz = roi[2];
    float sx = roi[3], sy = roi[4], sz = roi[5];
    float h  = roi[6];

    int i0 = j / 36, i1 = (j / 6) % 6, i2 = j % 6;
    float lx = (i0 + 0.5f) / 6.0f * sx - sx * 0.5f;
    float ly = (i1 + 0.5f) / 6.0f * sy - sy * 0.5f;
    float lz = (i2 + 0.5f) / 6.0f * sz - sz * 0.5f;

    float ch = cosf(h), sh = sinf(h);
    float gx = lx * ch - ly * sh + cx;
    float gy = lx * sh + ly * ch + cy;
    float gz = lz + cz;

    // floor((p - PCR)/VOX) then floor(/STRIDE), exactly as reference
    int vx = (int)floorf(floorf((gx - 0.0f)  / 0.05f) / 4.0f);
    int vy = (int)floorf(floorf((gy + 40.0f) / 0.05f) / 4.0f);
    int vz = (int)floorf(floorf((gz + 3.0f)  / 0.1f)  / 4.0f);

    __shared__ int s_pidx[27];
    int tid = threadIdx.x;
    if (tid < 27) {
        int dz = tid / 9 - 1, dy = (tid / 3) % 3 - 1, dx = tid % 3 - 1;
        int nz = vz + dz, ny = vy + dy, nx = vx + dx;
        int p = -1;
        if ((unsigned)nz < DZ && (unsigned)ny < DY && (unsigned)nx < DX) {
            p = g_v2p[br][((b * DZ + nz) * DY + ny) * DX + nx];
            if (p >= 0) {
                // voxel center (coords[p] == (b,nz,ny,nx) by construction)
                float px = (nx + 0.5f) * 0.2f + 0.0f;
                float py = (ny + 0.5f) * 0.2f - 40.0f;
                float pz = (nz + 0.5f) * 0.4f - 3.0f;
                float d2 = (px - gx) * (px - gx) + (py - gy) * (py - gy)
                         + (pz - gz) * (pz - gz);
                if (!(d2 < 0.16f)) p = -1;
            }
        }
        s_pidx[tid] = p;
    }
    __syncthreads();

    float cnt = 0.0f, sum = 0.0f;
    #pragma unroll
    for (int k = 0; k < 27; k++) {
        int p = s_pidx[k];
        if (p >= 0) {
            cnt += 1.0f;
            sum += feats[(size_t)p * Cc + tid];
        }
    }
    g_pooled[br][(size_t)m * Cc + tid] = sum / fmaxf(cnt, 1.0f);
}

// ---------------------------------------------------------------------------
// Per-ROI: mean over 216 grid points per channel (both branches),
// normalize each, dot, abs.
// ---------------------------------------------------------------------------
__global__ __launch_bounds__(64)
void roi_kernel() {
    int r = blockIdx.x;
    int c = threadIdx.x;

    float a = 0.0f, d = 0.0f;
    const float* p0 = &g_pooled[0][(size_t)r * G3 * Cc + c];
    const float* p1 = &g_pooled[1][(size_t)r * G3 * Cc + c];
    for (int j = 0; j < G3; j++) {
        a += p0[(size_t)j * Cc];
        d += p1[(size_t)j * Cc];
    }
    a /= (float)G3;
    d /= (float)G3;

    __shared__ float saa[64], sbb[64], sab[64];
    saa[c] = a * a;
    sbb[c] = d * d;
    sab[c] = a * d;
    __syncthreads();
    for (int s = 32; s > 0; s >>= 1) {
        if (c < s) {
            saa[c] += saa[c + s];
            sbb[c] += sbb[c + s];
            sab[c] += sab[c + s];
        }
        __syncthreads();
    }
    if (c == 0) {
        float na = fmaxf(sqrtf(saa[0]), 1e-12f);
        float nb = fmaxf(sqrtf(sbb[0]), 1e-12f);
        g_roi[r] = fabsf(sab[0] / (na * nb));
    }
}

__global__ void final_kernel(float* __restrict__ out) {
    float s = 0.0f;
    for (int r = 0; r < RR; r++) s += g_roi[r];
    out[0] = s / (float)RR;
}

// ---------------------------------------------------------------------------
extern "C" void kernel_launch(void* const* d_in, const int* in_sizes, int n_in,
                              void* d_out, int out_size) {
    const float* gt = (const float*)d_in[0];
    const int*   cd = (const int*)  d_in[1];
    const float* fd = (const float*)d_in[2];
    const int*   cs = (const int*)  d_in[3];
    const float* fs = (const float*)d_in[4];
    int ntot = in_sizes[1] / 4;   // 200000

    // Reset the v2p maps to -1 (0xFF bytes)
    void* pmap = nullptr;
    cudaGetSymbolAddress(&pmap, g_v2p);
    cudaMemsetAsync(pmap, 0xFF, sizeof(g_v2p), 0);

    dim3 sgrid((ntot + 255) / 256, 2);
    scatter_kernel<<<sgrid, 256>>>(cd, cs, ntot);

    dim3 pgrid(NPTS, 2);
    pool_kernel<<<pgrid, 64>>>(gt, fd, fs);

    roi_kernel<<<RR, 64>>>();
    final_kernel<<<1, 1>>>((float*)d_out);
}

// round 17
// speedup vs baseline: 1.0116x; 1.0116x over previous
#include <cuda_runtime.h>

// Problem constants (match reference)
#define Bb   2
#define NGT  64
#define Gp   6
#define G3   216            // Gp^3
#define Cc   64
#define DZ   10
#define DY   400
#define DX   352
#define NPTS (Bb*NGT*G3)    // 27648 grid points (per branch)
#define NMAP (Bb*DZ*DY*DX)  // 2,816,000 cells
#define RR   (Bb*NGT)       // 128 ROIs

// Scratch (static device globals — no allocation allowed)
__device__ int   g_v2p[2][NMAP];       // voxel->point index map, -1 = empty
__device__ float g_pooled[2][NPTS*Cc]; // per-grid-point pooled feature
__device__ float g_roi[RR];            // per-ROI |cosine|

// ---------------------------------------------------------------------------
// Scatter voxel index into dense map. atomicMax == last-write-wins for the
// ascending arange the reference scatters (matches XLA CPU scatter order).
// blockIdx.y selects branch (0=dir, 1=dsr).
// ---------------------------------------------------------------------------
__global__ void scatter_kernel(const int* __restrict__ c0,
                               const int* __restrict__ c1, int ntot) {
    int i = blockIdx.x * blockDim.x + threadIdx.x;
    if (i >= ntot) return;
    const int* c = (blockIdx.y ? c1 : c0) + (size_t)i * 4;
    int flat = ((c[0] * DZ + c[1]) * DY + c[2]) * DX + c[3];
    atomicMax(&g_v2p[blockIdx.y][flat], i);
}

// ---------------------------------------------------------------------------
// Pooling: one block per (grid point, branch). 64 threads = one per channel.
// Threads 0..26 resolve the 27 neighbor cells into shared, then every thread
// accumulates its channel over the valid neighbors.
// ---------------------------------------------------------------------------
__global__ __launch_bounds__(64)
void pool_kernel(const float* __restrict__ gt,
                 const float* __restrict__ f0,
                 const float* __restrict__ f1) {
    int m  = blockIdx.x;
    int br = blockIdx.y;
    const float* feats = br ? f1 : f0;

    int r = m / G3;
    int j = m - r * G3;
    int b = r / NGT;

    const float* roi = gt + (size_t)r * 8;
    float cx = roi[0], cy = roi[1], cz = roi[2];
    float sx = roi[3], sy = roi[4], sz = roi[5];
    float h  = roi[6];

    int i0 = j / 36, i1 = (j / 6) % 6, i2 = j % 6;
    float lx = (i0 + 0.5f) / 6.0f * sx - sx * 0.5f;
    float ly = (i1 + 0.5f) / 6.0f * sy - sy * 0.5f;
    float lz = (i2 + 0.5f) / 6.0f * sz - sz * 0.5f;

    float ch = cosf(h), sh = sinf(h);
    float gx = lx * ch - ly * sh + cx;
    float gy = lx * sh + ly * ch + cy;
    float gz = lz + cz;

    // floor((p - PCR)/VOX) then floor(/STRIDE), exactly as reference
    int vx = (int)floorf(floorf((gx - 0.0f)  / 0.05f) / 4.0f);
    int vy = (int)floorf(floorf((gy + 40.0f) / 0.05f) / 4.0f);
    int vz = (int)floorf(floorf((gz + 3.0f)  / 0.1f)  / 4.0f);

    __shared__ int s_pidx[27];
    int tid = threadIdx.x;
    if (tid < 27) {
        int dz = tid / 9 - 1, dy = (tid / 3) % 3 - 1, dx = tid % 3 - 1;
        int nz = vz + dz, ny = vy + dy, nx = vx + dx;
        int p = -1;
        if ((unsigned)nz < DZ && (unsigned)ny < DY && (unsigned)nx < DX) {
            p = g_v2p[br][((b * DZ + nz) * DY + ny) * DX + nx];
            if (p >= 0) {
                // voxel center (coords[p] == (b,nz,ny,nx) by construction)
                float px = (nx + 0.5f) * 0.2f + 0.0f;
                float py = (ny + 0.5f) * 0.2f - 40.0f;
                float pz = (nz + 0.5f) * 0.4f - 3.0f;
                float d2 = (px - gx) * (px - gx) + (py - gy) * (py - gy)
                         + (pz - gz) * (pz - gz);
                if (!(d2 < 0.16f)) p = -1;
            }
        }
        s_pidx[tid] = p;
    }
    __syncthreads();

    float cnt = 0.0f, sum = 0.0f;
    #pragma unroll
    for (int k = 0; k < 27; k++) {
        int p = s_pidx[k];
        if (p >= 0) {
            cnt += 1.0f;
            sum += feats[(size_t)p * Cc + tid];
        }
    }
    g_pooled[br][(size_t)m * Cc + tid] = sum / fmaxf(cnt, 1.0f);
}

// ---------------------------------------------------------------------------
// Per-ROI: mean over 216 grid points per channel (both branches),
// normalize each, dot, abs.
// ---------------------------------------------------------------------------
__global__ __launch_bounds__(64)
void roi_kernel() {
    int r = blockIdx.x;
    int c = threadIdx.x;

    float a = 0.0f, d = 0.0f;
    const float* p0 = &g_pooled[0][(size_t)r * G3 * Cc + c];
    const float* p1 = &g_pooled[1][(size_t)r * G3 * Cc + c];
    for (int j = 0; j < G3; j++) {
        a += p0[(size_t)j * Cc];
        d += p1[(size_t)j * Cc];
    }
    a /= (float)G3;
    d /= (float)G3;

    __shared__ float saa[64], sbb[64], sab[64];
    saa[c] = a * a;
    sbb[c] = d * d;
    sab[c] = a * d;
    __syncthreads();
    for (int s = 32; s > 0; s >>= 1) {
        if (c < s) {
            saa[c] += saa[c + s];
            sbb[c] += sbb[c + s];
            sab[c] += sab[c + s];
        }
        __syncthreads();
    }
    if (c == 0) {
        float na = fmaxf(sqrtf(saa[0]), 1e-12f);
        float nb = fmaxf(sqrtf(sbb[0]), 1e-12f);
        g_roi[r] = fabsf(sab[0] / (na * nb));
    }
}

__global__ void final_kernel(float* __restrict__ out) {
    float s = 0.0f;
    for (int r = 0; r < RR; r++) s += g_roi[r];
    out[0] = s / (float)RR;
}

// ---------------------------------------------------------------------------
extern "C" void kernel_launch(void* const* d_in, const int* in_sizes, int n_in,
                              void* d_out, int out_size) {
    const float* gt = (const float*)d_in[0];
    const int*   cd = (const int*)  d_in[1];
    const float* fd = (const float*)d_in[2];
    const int*   cs = (const int*)  d_in[3];
    const float* fs = (const float*)d_in[4];
    int ntot = in_sizes[1] / 4;   // 200000

    // Reset the v2p maps to -1 (0xFF bytes)
    void* pmap = nullptr;
    cudaGetSymbolAddress(&pmap, g_v2p);
    cudaMemsetAsync(pmap, 0xFF, sizeof(g_v2p), 0);

    dim3 sgrid((ntot + 255) / 256, 2);
    scatter_kernel<<<sgrid, 256>>>(cd, cs, ntot);

    dim3 pgrid(NPTS, 2);
    pool_kernel<<<pgrid, 64>>>(gt, fd, fs);

    roi_kernel<<<RR, 64>>>();
    final_kernel<<<1, 1>>>((float*)d_out);
}